// round 15
// baseline (speedup 1.0000x reference)
#include <cuda_runtime.h>
#include <math.h>

#define ESL    4096
#define BATCH  64
#define EHS    256
#define SLICES 9
#define NBLK   (BATCH * SLICES)   // 576 blocks ~= one wave at 4 blocks/SM
#define NSTREAM 72                // 72 warp-streams per batch
#define TASK_ROWS 8
#define NTASK  (ESL / TASK_ROWS)  // 512 tasks of 8 contiguous rows

// block-level partials: g_pc[b][slice][ch], g_pz[b][slice]  (589 KB -> L2-hot)
__device__ float g_pc[BATCH * SLICES * EHS];
__device__ float g_pz[BATCH * SLICES];
__device__ int   g_cnt[BATCH];    // zero-init; consumer resets each run

__device__ __forceinline__ float dot4(float4 a, float4 b) {
    return a.x*b.x + a.y*b.y + a.z*b.z + a.w*b.w;
}

__global__ __launch_bounds__(256, 4)
void attn_fused(const float* __restrict__ si,   // (1,64,256)
                const float* __restrict__ h,    // (4096,64,256)
                const float* __restrict__ W,    // (1,512) [Wd|We]
                const float* __restrict__ bias, // (1,)
                float* __restrict__ out)        // (1,64,256)
{
    const int b     = blockIdx.x & 63;
    const int slice = blockIdx.x >> 6;          // 0..8
    const int tid   = threadIdx.x;
    const int w     = tid >> 5;
    const int lane  = tid & 31;

    const float4* We4 = (const float4*)(W + EHS);
    const float4 we0 = We4[lane];
    const float4 we1 = We4[lane + 32];

    // d = dot(si[b], Wd) + bias
    const float4* Wd4 = (const float4*)W;
    const float4* si4 = (const float4*)(si + b * EHS);
    float4 a0 = si4[lane], a1 = si4[lane + 32];
    float4 w0 = Wd4[lane], w1 = Wd4[lane + 32];
    float d = dot4(a0, w0) + dot4(a1, w1);
    #pragma unroll
    for (int o = 16; o; o >>= 1) d += __shfl_xor_sync(0xFFFFFFFFu, d, o);
    d += bias[0];

    const size_t row_stride = (size_t)BATCH * EHS;  // floats between s and s+1
    const float* hb = h + (size_t)b * EHS;
    const int j = slice * 8 + w;                    // warp stream id, 0..71

    float Z = 0.0f;
    float4 c0 = make_float4(0.f, 0.f, 0.f, 0.f);
    float4 c1 = make_float4(0.f, 0.f, 0.f, 0.f);

    // R6-style mainloop: 8 contiguous rows per task, paired-row ILP
    for (int t = j; t < NTASK; t += NSTREAM) {
        const float* base = hb + (size_t)(t * TASK_ROWS) * row_stride;
        #pragma unroll
        for (int r = 0; r < TASK_ROWS; r += 2) {
            const float4* p0 = (const float4*)(base + (size_t)r       * row_stride);
            const float4* p1 = (const float4*)(base + (size_t)(r + 1) * row_stride);
            const float4 h00 = p0[lane], h01 = p0[lane + 32];
            const float4 h10 = p1[lane], h11 = p1[lane + 32];

            float e0 = dot4(h00, we0) + dot4(h01, we1);
            float e1 = dot4(h10, we0) + dot4(h11, we1);
            #pragma unroll
            for (int o = 16; o; o >>= 1) {
                e0 += __shfl_xor_sync(0xFFFFFFFFu, e0, o);
                e1 += __shfl_xor_sync(0xFFFFFFFFu, e1, o);
            }
            const float q0 = __expf(fmaxf(e0 + d, 0.0f));
            const float q1 = __expf(fmaxf(e1 + d, 0.0f));
            Z += q0 + q1;
            c0.x = fmaf(q0, h00.x, fmaf(q1, h10.x, c0.x));
            c0.y = fmaf(q0, h00.y, fmaf(q1, h10.y, c0.y));
            c0.z = fmaf(q0, h00.z, fmaf(q1, h10.z, c0.z));
            c0.w = fmaf(q0, h00.w, fmaf(q1, h10.w, c0.w));
            c1.x = fmaf(q0, h01.x, fmaf(q1, h11.x, c1.x));
            c1.y = fmaf(q0, h01.y, fmaf(q1, h11.y, c1.y));
            c1.z = fmaf(q0, h01.z, fmaf(q1, h11.z, c1.z));
            c1.w = fmaf(q0, h01.w, fmaf(q1, h11.w, c1.w));
        }
    }

    // ---- block combine: 8 warps -> 1 partial ----
    __shared__ __align__(16) float4 s_c4[8][EHS / 4];   // 8 KB
    __shared__ float s_z[8];
    __shared__ bool  s_last;
    s_c4[w][lane]      = c0;
    s_c4[w][lane + 32] = c1;
    if (lane == 0) s_z[w] = Z;
    __syncthreads();

    if (tid < 64) {
        float4 acc = s_c4[0][tid];
        #pragma unroll
        for (int p = 1; p < 8; p++) {
            float4 u = s_c4[p][tid];
            acc.x += u.x; acc.y += u.y; acc.z += u.z; acc.w += u.w;
        }
        ((float4*)(g_pc + ((size_t)b * SLICES + slice) * EHS))[tid] = acc;
    }
    if (tid == 0) {
        float zt = 0.0f;
        #pragma unroll
        for (int p = 0; p < 8; p++) zt += s_z[p];
        g_pz[b * SLICES + slice] = zt;
    }

    // ---- fused tail: last block per batch reduces its 9 partials ----
    __threadfence();
    __syncthreads();
    if (tid == 0) s_last = (atomicAdd(&g_cnt[b], 1) == SLICES - 1);
    __syncthreads();
    if (s_last) {
        __threadfence();   // acquire: all 9 partials visible
        float z = 0.0f;
        #pragma unroll
        for (int s = 0; s < SLICES; s++) z += g_pz[b * SLICES + s];
        float c = 0.0f;
        #pragma unroll
        for (int s = 0; s < SLICES; s++)
            c += g_pc[((size_t)b * SLICES + s) * EHS + tid];
        out[b * EHS + tid] = c / z;
        if (tid == 0) g_cnt[b] = 0;   // reset for next graph replay
    }
}

extern "C" void kernel_launch(void* const* d_in, const int* in_sizes, int n_in,
                              void* d_out, int out_size)
{
    const float* si   = (const float*)d_in[0];  // (1,64,256)
    const float* h    = (const float*)d_in[1];  // (4096,64,256)
    const float* W    = (const float*)d_in[2];  // (1,512)
    const float* bias = (const float*)d_in[3];  // (1,)
    float* out = (float*)d_out;                 // (1,64,256)

    attn_fused<<<NBLK, 256>>>(si, h, W, bias, out);
}